// round 6
// baseline (speedup 1.0000x reference)
#include <cuda_runtime.h>
#include <math_constants.h>

#define EPS_WH 1e-07f
#define MAX_WH 10000000.0f
#define THREADS 256
#define SPLIT 4              // blocks per batch row

// Scratch: per-(batch,split) argmax keys, per-run completion counter.
__device__ unsigned long long g_keys[4096 * SPLIT];
__device__ int g_count;      // zero-initialized; reset by last block each run

__device__ __forceinline__ float clip_wh(float v) {
    return fminf(fmaxf(v, EPS_WH), MAX_WH);
}

// Map float bits to a monotonically ordered uint32 (standard sortable trick).
__device__ __forceinline__ unsigned int f2sortable(float f) {
    unsigned int u = __float_as_uint(f);
    return (u & 0x80000000u) ? ~u : (u | 0x80000000u);
}

__device__ __forceinline__ float gwd_loss_one(
    const float* __restrict__ ab, const float* __restrict__ trig,
    const float* __restrict__ center, const float* __restrict__ target,
    int b, int idx, int HW)
{
    const float* abb = ab   + (size_t)b * 2 * HW;
    const float* tgb = trig + (size_t)b * 2 * HW;
    float a1    = __ldg(&abb[idx]);
    float a2    = __ldg(&abb[HW + idx]);
    float sin2A = __ldg(&tgb[idx]);
    float cos2A = __ldg(&tgb[HW + idx]);

    // deg roundtrip in the reference is the identity; stay in radians
    float r_p = 0.5f * atan2f(sin2A, cos2A);
    float xp = center[2 * b], yp = center[2 * b + 1];
    float s1p = 0.5f * clip_wh(2.0f * a1);
    float s2p = 0.5f * clip_wh(2.0f * a2);
    float cp = cosf(r_p), sp = sinf(r_p);

    float xt = target[5 * b + 0];
    float yt = target[5 * b + 1];
    float s1t = 0.5f * clip_wh(target[5 * b + 2]);
    float s2t = 0.5f * clip_wh(target[5 * b + 3]);
    float r_t = target[5 * b + 4] * (CUDART_PI_F / 180.0f);
    float ct = cosf(r_t), st = sinf(r_t);

    float dx = xp - xt, dy = yp - yt;
    float xy_dist = dx * dx + dy * dy;

    float sp1_2 = s1p * s1p, sp2_2 = s2p * s2p;
    float st1_2 = s1t * s1t, st2_2 = s2t * s2t;

    float Ap = sp1_2 * cp * cp + sp2_2 * sp * sp;
    float Bp = sp1_2 * sp * sp + sp2_2 * cp * cp;
    float Cp = (sp1_2 - sp2_2) * cp * sp;

    float At = st1_2 * ct * ct + st2_2 * st * st;
    float Bt = st1_2 * st * st + st2_2 * ct * ct;
    float Ct = (st1_2 - st2_2) * ct * st;

    float tr_pt = Ap * At + Bp * Bt + 2.0f * Cp * Ct;
    float det_sqrt = sqrtf(fmaxf(s1p * s2p * s1t * s2t, 0.0f));

    float whr = sp1_2 + sp2_2 + st1_2 + st2_2
              - 2.0f * sqrtf(fmaxf(tr_pt + 2.0f * det_sqrt, 0.0f));

    float dist = fmaxf(xy_dist + whr, 0.0f);
    return 1.0f - 1.0f / (1.0f + dist);
}

// SPLIT blocks per batch row: fine-grained streaming argmax (reduces the
// partial-wave tail). The globally-last block runs all epilogues + the mean.
__global__ void __launch_bounds__(THREADS)
gwd_fused_kernel(const float* __restrict__ hm,
                 const float* __restrict__ ab,
                 const float* __restrict__ trig,
                 const float* __restrict__ center,
                 const float* __restrict__ target,
                 float* __restrict__ out,
                 int HW, int B)
{
    const int blk = blockIdx.x;
    const int b   = blk >> 2;          // batch row (SPLIT = 4)
    const int qtr = blk & (SPLIT - 1); // which quarter of the row
    const int t   = threadIdx.x;

    const int n4q = HW >> 4;           // float4s per quarter (HW/4/4)
    const int q0  = qtr * n4q;         // starting float4 within row

    const float4* hm4 = reinterpret_cast<const float4*>(hm + (size_t)b * HW);

    float best = -CUDART_INF_F;
    int bidx = 0;

    // Branchless scan; one fully front-batched round of loads for n4q=1024.
    #pragma unroll 4
    for (int i = t; i < n4q; i += THREADS) {
        float4 v = hm4[q0 + i];
        int base = (q0 + i) << 2;      // global index within the row

        float m = fmaxf(fmaxf(v.x, v.y), fmaxf(v.z, v.w));

        int idx4 = (v.z == m) ? (base + 2) : (base + 3);
        idx4     = (v.y == m) ? (base + 1) : idx4;
        idx4     = (v.x == m) ?  base      : idx4;

        bidx = (m > best) ? idx4 : bidx;   // strict > keeps earliest i on ties
        best = fmaxf(best, m);
    }

    // Pack (sortable value | ~idx): max picks max value, ties -> smallest idx.
    unsigned long long key =
        ((unsigned long long)f2sortable(best) << 32) |
        (unsigned long long)(unsigned int)(~bidx);

    #pragma unroll
    for (int off = 16; off > 0; off >>= 1) {
        unsigned long long o = __shfl_xor_sync(0xffffffffu, key, off);
        key = (o > key) ? o : key;
    }

    __shared__ unsigned long long skey[THREADS / 32];
    if ((t & 31) == 0) skey[t >> 5] = key;
    __syncthreads();
    if (t < 32) {
        unsigned long long k = (t < THREADS / 32) ? skey[t] : 0ull;
        #pragma unroll
        for (int off = 16; off > 0; off >>= 1) {
            unsigned long long o = __shfl_xor_sync(0xffffffffu, k, off);
            k = (o > k) ? o : k;
        }
        if (t == 0) skey[0] = k;
    }
    __syncthreads();

    if (t == 0) g_keys[blk] = skey[0];

    // ---- last-block-done: all epilogues + deterministic mean ----
    __shared__ bool amLast;
    if (t == 0) {
        __threadfence();
        amLast = (atomicAdd(&g_count, 1) == gridDim.x - 1);
    }
    __syncthreads();

    if (amLast) {
        __threadfence();  // acquire: make peer g_keys writes visible

        // 256 threads x 4 batches each: combine keys, gather, loss.
        float acc = 0.0f;
        const int nb = B / THREADS;    // 4
        #pragma unroll
        for (int k = 0; k < nb; k++) {
            int bb = t + k * THREADS;
            unsigned long long kk = __ldcg(&g_keys[bb * SPLIT]);
            #pragma unroll
            for (int s = 1; s < SPLIT; s++) {
                unsigned long long o = __ldcg(&g_keys[bb * SPLIT + s]);
                kk = (o > kk) ? o : kk;
            }
            int idx = (int)(~((unsigned int)(kk & 0xffffffffu)));
            acc += gwd_loss_one(ab, trig, center, target, bb, idx, HW);
        }

        __shared__ float sh[THREADS];
        sh[t] = acc;
        __syncthreads();
        #pragma unroll
        for (int s = THREADS / 2; s > 0; s >>= 1) {
            if (t < s) sh[t] += sh[t + s];
            __syncthreads();
        }
        if (t == 0) {
            out[0] = sh[0] / (float)B;
            g_count = 0;  // reset for next graph replay
        }
    }
}

extern "C" void kernel_launch(void* const* d_in, const int* in_sizes, int n_in,
                              void* d_out, int out_size)
{
    const float* hm     = (const float*)d_in[0];  // (B,1,H,W)
    const float* ab     = (const float*)d_in[1];  // (B,2,H,W)
    const float* trig   = (const float*)d_in[2];  // (B,2,H,W)
    const float* center = (const float*)d_in[3];  // (B,2)
    const float* target = (const float*)d_in[4];  // (B,5)
    float* out = (float*)d_out;

    const int B  = in_sizes[4] / 5;
    const int HW = in_sizes[0] / B;

    gwd_fused_kernel<<<B * SPLIT, THREADS>>>(hm, ab, trig, center, target,
                                             out, HW, B);
}

// round 7
// speedup vs baseline: 1.2342x; 1.2342x over previous
#include <cuda_runtime.h>
#include <math_constants.h>

#define EPS_WH 1e-07f
#define MAX_WH 10000000.0f
#define THREADS 512
#define VPT 8                 // float4s per thread (512*8*4 = 16384 = HW)

// Scratch: per-block argmax keys + completion counter.
__device__ unsigned long long g_keys[4096];
__device__ int g_count;       // zero-initialized; reset by last block each run

__device__ __forceinline__ float clip_wh(float v) {
    return fminf(fmaxf(v, EPS_WH), MAX_WH);
}

// Map float bits to a monotonically ordered uint32 (standard sortable trick).
__device__ __forceinline__ unsigned int f2sortable(float f) {
    unsigned int u = __float_as_uint(f);
    return (u & 0x80000000u) ? ~u : (u | 0x80000000u);
}

__device__ __forceinline__ float gwd_loss_one(
    const float* __restrict__ ab, const float* __restrict__ trig,
    const float* __restrict__ center, const float* __restrict__ target,
    int b, int idx, int HW)
{
    const float* abb = ab   + (size_t)b * 2 * HW;
    const float* tgb = trig + (size_t)b * 2 * HW;
    float a1    = __ldg(&abb[idx]);
    float a2    = __ldg(&abb[HW + idx]);
    float sin2A = __ldg(&tgb[idx]);
    float cos2A = __ldg(&tgb[HW + idx]);

    // deg roundtrip in the reference is the identity; stay in radians
    float r_p = 0.5f * atan2f(sin2A, cos2A);
    float xp = center[2 * b], yp = center[2 * b + 1];
    float s1p = 0.5f * clip_wh(2.0f * a1);
    float s2p = 0.5f * clip_wh(2.0f * a2);
    float cp = cosf(r_p), sp = sinf(r_p);

    float xt = target[5 * b + 0];
    float yt = target[5 * b + 1];
    float s1t = 0.5f * clip_wh(target[5 * b + 2]);
    float s2t = 0.5f * clip_wh(target[5 * b + 3]);
    float r_t = target[5 * b + 4] * (CUDART_PI_F / 180.0f);
    float ct = cosf(r_t), st = sinf(r_t);

    float dx = xp - xt, dy = yp - yt;
    float xy_dist = dx * dx + dy * dy;

    float sp1_2 = s1p * s1p, sp2_2 = s2p * s2p;
    float st1_2 = s1t * s1t, st2_2 = s2t * s2t;

    float Ap = sp1_2 * cp * cp + sp2_2 * sp * sp;
    float Bp = sp1_2 * sp * sp + sp2_2 * cp * cp;
    float Cp = (sp1_2 - sp2_2) * cp * sp;

    float At = st1_2 * ct * ct + st2_2 * st * st;
    float Bt = st1_2 * st * st + st2_2 * ct * ct;
    float Ct = (st1_2 - st2_2) * ct * st;

    float tr_pt = Ap * At + Bp * Bt + 2.0f * Cp * Ct;
    float det_sqrt = sqrtf(fmaxf(s1p * s2p * s1t * s2t, 0.0f));

    float whr = sp1_2 + sp2_2 + st1_2 + st2_2
              - 2.0f * sqrtf(fmaxf(tr_pt + 2.0f * det_sqrt, 0.0f));

    float dist = fmaxf(xy_dist + whr, 0.0f);
    return 1.0f - 1.0f / (1.0f + dist);
}

// One block per batch row. 512 threads x 8 float4s, all loads front-batched
// into explicit registers (MLP_p1 = 8). Last block runs all epilogues + mean.
__global__ void __launch_bounds__(THREADS, 2)
gwd_fused_kernel(const float* __restrict__ hm,
                 const float* __restrict__ ab,
                 const float* __restrict__ trig,
                 const float* __restrict__ center,
                 const float* __restrict__ target,
                 float* __restrict__ out,
                 int HW, int B)
{
    const int b = blockIdx.x;
    const int t = threadIdx.x;

    const float4* hm4 = reinterpret_cast<const float4*>(hm + (size_t)b * HW);

    // ---- front-batched load burst: 8 independent LDG.128 (streaming) ----
    float4 v[VPT];
    #pragma unroll
    for (int k = 0; k < VPT; k++)
        v[k] = __ldcs(&hm4[t + k * THREADS]);

    // ---- branchless consume: FMNMX tree + SEL chains ----
    float best = -CUDART_INF_F;
    int bidx = 0;
    #pragma unroll
    for (int k = 0; k < VPT; k++) {
        int base = (t + k * THREADS) << 2;
        float m = fmaxf(fmaxf(v[k].x, v[k].y), fmaxf(v[k].z, v[k].w));

        int idx4 = (v[k].z == m) ? (base + 2) : (base + 3);
        idx4     = (v[k].y == m) ? (base + 1) : idx4;
        idx4     = (v[k].x == m) ?  base      : idx4;

        bidx = (m > best) ? idx4 : bidx;   // strict > keeps earliest k on ties
        best = fmaxf(best, m);
    }

    // Pack (sortable value | ~idx): max picks max value, ties -> smallest idx.
    // (k-ordering equals index-ordering here since idx grows with k.)
    unsigned long long key =
        ((unsigned long long)f2sortable(best) << 32) |
        (unsigned long long)(unsigned int)(~bidx);

    #pragma unroll
    for (int off = 16; off > 0; off >>= 1) {
        unsigned long long o = __shfl_xor_sync(0xffffffffu, key, off);
        key = (o > key) ? o : key;
    }

    __shared__ unsigned long long skey[THREADS / 32];   // 16 warps
    if ((t & 31) == 0) skey[t >> 5] = key;
    __syncthreads();
    if (t < 32) {
        unsigned long long k = (t < THREADS / 32) ? skey[t] : 0ull;
        #pragma unroll
        for (int off = 8; off > 0; off >>= 1) {
            unsigned long long o = __shfl_xor_sync(0xffffffffu, k, off);
            k = (o > k) ? o : k;
        }
        if (t == 0) g_keys[b] = k;
    }

    // ---- last-block-done: all epilogues + deterministic mean ----
    __shared__ bool amLast;
    __syncthreads();
    if (t == 0) {
        __threadfence();
        amLast = (atomicAdd(&g_count, 1) == gridDim.x - 1);
    }
    __syncthreads();

    if (amLast) {
        __threadfence();  // make peer g_keys writes visible

        float acc = 0.0f;
        for (int bb = t; bb < B; bb += THREADS) {
            unsigned long long kk = __ldcg(&g_keys[bb]);
            int idx = (int)(~((unsigned int)(kk & 0xffffffffu)));
            acc += gwd_loss_one(ab, trig, center, target, bb, idx, HW);
        }

        __shared__ float sh[THREADS];
        sh[t] = acc;
        __syncthreads();
        #pragma unroll
        for (int s = THREADS / 2; s > 0; s >>= 1) {
            if (t < s) sh[t] += sh[t + s];
            __syncthreads();
        }
        if (t == 0) {
            out[0] = sh[0] / (float)B;
            g_count = 0;  // reset for next graph replay
        }
    }
}

extern "C" void kernel_launch(void* const* d_in, const int* in_sizes, int n_in,
                              void* d_out, int out_size)
{
    const float* hm     = (const float*)d_in[0];  // (B,1,H,W)
    const float* ab     = (const float*)d_in[1];  // (B,2,H,W)
    const float* trig   = (const float*)d_in[2];  // (B,2,H,W)
    const float* center = (const float*)d_in[3];  // (B,2)
    const float* target = (const float*)d_in[4];  // (B,5)
    float* out = (float*)d_out;

    const int B  = in_sizes[4] / 5;
    const int HW = in_sizes[0] / B;   // 16384 = THREADS * VPT * 4

    gwd_fused_kernel<<<B, THREADS>>>(hm, ab, trig, center, target, out, HW, B);
}